// round 6
// baseline (speedup 1.0000x reference)
#include <cuda_runtime.h>
#include <cuda_fp16.h>
#include <cstdint>

#define BSZ   8192
#define HID   1024
#define KDIM  2048
#define LVL   64
#define NGATE 4096
#define NLEV  128

// -------- scratch (static __device__, no allocations) --------
__device__ __half g_A[(size_t)BSZ * KDIM];            // 33.5 MB fp16 combined input
__device__ __half g_W[(size_t)(NGATE + NLEV) * KDIM]; // 17.3 MB fp16 reordered weights
__device__ float  g_lev[(size_t)BSZ * NLEV];          // raw level logits
__device__ float  g_ih[(size_t)BSZ * LVL];
__device__ float  g_fh[(size_t)BSZ * LVL];

// -------- prep: fp32 -> fp16 combined activation --------
__global__ void prep_A(const float* __restrict__ inp, const float* __restrict__ hprev) {
    int idx = blockIdx.x * blockDim.x + threadIdx.x;   // float4 index, 512 per row
    int row = idx >> 9;
    int c4  = idx & 511;
    const float* src = (c4 < 256) ? (inp + (size_t)row * 1024 + c4 * 4)
                                  : (hprev + (size_t)row * 1024 + (c4 - 256) * 4);
    float4 v = *reinterpret_cast<const float4*>(src);
    __half2* dst = reinterpret_cast<__half2*>(g_A + (size_t)row * KDIM + c4 * 4);
    dst[0] = __floats2half2_rn(v.x, v.y);
    dst[1] = __floats2half2_rn(v.z, v.w);
}

// -------- prep: fp32 -> fp16 weights, gate-interleaved rows --------
__global__ void prep_W(const float* __restrict__ wl, const float* __restrict__ wv) {
    int idx = blockIdx.x * blockDim.x + threadIdx.x;   // float4 index
    int n  = idx >> 9;
    int c4 = idx & 511;
    const float* src;
    if (n < NGATE) src = wl + (size_t)((n & 3) * 1024 + (n >> 2)) * KDIM + c4 * 4;
    else           src = wv + (size_t)(n - NGATE) * KDIM + c4 * 4;
    float4 v = *reinterpret_cast<const float4*>(src);
    __half2* dst = reinterpret_cast<__half2*>(g_W + (size_t)n * KDIM + c4 * 4);
    dst[0] = __floats2half2_rn(v.x, v.y);
    dst[1] = __floats2half2_rn(v.z, v.w);
}

// -------- GEMM --------
#define BM 128
#define BN 128
#define BK 32
#define LDS 40   // padded half stride (80B) -> conflict-free ldmatrix

__device__ __forceinline__ uint32_t smem_u32(const void* p) {
    return (uint32_t)__cvta_generic_to_shared(p);
}
__device__ __forceinline__ float sigmoidf_(float x) { return 1.0f / (1.0f + __expf(-x)); }

// MODE 0: main gates GEMM + fused ON-LSTM epilogue -> d_out
// MODE 1: level GEMM -> g_lev raw
template <int MODE>
__global__ __launch_bounds__(256, 2) void gemm_kernel(const float* __restrict__ c_prev,
                                                      float* __restrict__ d_out) {
    __shared__ __half As[2][BM * LDS];
    __shared__ __half Bs[2][BM * LDS];
    const int tid   = threadIdx.x;
    const int lane  = tid & 31;
    const int wid   = tid >> 5;
    const int warpM = wid >> 2;   // 0..1 (64 rows each)
    const int warpN = wid & 3;    // 0..3 (32 cols each)
    const int bm    = blockIdx.y;
    const int bn    = blockIdx.x;
    const int nOff  = (MODE == 1) ? NGATE : 0;

    const __half* Ag = g_A + (size_t)(bm * BM) * KDIM;
    const __half* Bg = g_W + (size_t)(nOff + bn * BN) * KDIM;

    float acc[4][4][4];
#pragma unroll
    for (int a = 0; a < 4; a++)
#pragma unroll
        for (int b = 0; b < 4; b++)
#pragma unroll
            for (int c = 0; c < 4; c++) acc[a][b][c] = 0.0f;

    const int KT = KDIM / BK;  // 64

    auto load_tile = [&](int buf, int kt) {
        int k0 = kt * BK;
#pragma unroll
        for (int i = 0; i < 2; i++) {
            int lin = tid + i * 256;
            int row = lin >> 2, ch = lin & 3;
            uint32_t da = smem_u32(&As[buf][row * LDS + ch * 8]);
            const __half* sa = Ag + (size_t)row * KDIM + k0 + ch * 8;
            asm volatile("cp.async.cg.shared.global [%0], [%1], 16;\n" ::"r"(da), "l"(sa));
            uint32_t db = smem_u32(&Bs[buf][row * LDS + ch * 8]);
            const __half* sb = Bg + (size_t)row * KDIM + k0 + ch * 8;
            asm volatile("cp.async.cg.shared.global [%0], [%1], 16;\n" ::"r"(db), "l"(sb));
        }
        asm volatile("cp.async.commit_group;\n");
    };

    load_tile(0, 0);
    for (int kt = 0; kt < KT; ++kt) {
        int buf = kt & 1;
        if (kt + 1 < KT) {
            load_tile(buf ^ 1, kt + 1);
            asm volatile("cp.async.wait_group 1;\n");
        } else {
            asm volatile("cp.async.wait_group 0;\n");
        }
        __syncthreads();
#pragma unroll
        for (int ks = 0; ks < 2; ++ks) {
            uint32_t afr[4][4];
#pragma unroll
            for (int mi = 0; mi < 4; ++mi) {
                int r  = warpM * 64 + mi * 16 + (lane & 15);
                int ch = ks * 2 + (lane >> 4);
                uint32_t addr = smem_u32(&As[buf][r * LDS + ch * 8]);
                asm volatile("ldmatrix.sync.aligned.m8n8.x4.shared.b16 {%0,%1,%2,%3}, [%4];"
                             : "=r"(afr[mi][0]), "=r"(afr[mi][1]), "=r"(afr[mi][2]), "=r"(afr[mi][3])
                             : "r"(addr));
            }
            uint32_t bfr[4][2];
#pragma unroll
            for (int np = 0; np < 2; ++np) {
                int r  = warpN * 32 + np * 16 + (lane & 15);
                int ch = ks * 2 + (lane >> 4);
                uint32_t addr = smem_u32(&Bs[buf][r * LDS + ch * 8]);
                uint32_t r0, r1, r2, r3;
                asm volatile("ldmatrix.sync.aligned.m8n8.x4.shared.b16 {%0,%1,%2,%3}, [%4];"
                             : "=r"(r0), "=r"(r1), "=r"(r2), "=r"(r3)
                             : "r"(addr));
                bfr[np * 2][0] = r0; bfr[np * 2 + 1][0] = r1;
                bfr[np * 2][1] = r2; bfr[np * 2 + 1][1] = r3;
            }
#pragma unroll
            for (int mi = 0; mi < 4; ++mi)
#pragma unroll
                for (int ni = 0; ni < 4; ++ni) {
                    asm volatile(
                        "mma.sync.aligned.m16n8k16.row.col.f32.f16.f16.f32 "
                        "{%0,%1,%2,%3}, {%4,%5,%6,%7}, {%8,%9}, {%0,%1,%2,%3};"
                        : "+f"(acc[mi][ni][0]), "+f"(acc[mi][ni][1]),
                          "+f"(acc[mi][ni][2]), "+f"(acc[mi][ni][3])
                        : "r"(afr[mi][0]), "r"(afr[mi][1]), "r"(afr[mi][2]), "r"(afr[mi][3]),
                          "r"(bfr[ni][0]), "r"(bfr[ni][1]));
                }
        }
        __syncthreads();
    }

    // -------- epilogue --------
    if (MODE == 1) {
        int rbase = bm * BM + warpM * 64;
#pragma unroll
        for (int mi = 0; mi < 4; mi++) {
            int r0 = rbase + mi * 16 + (lane >> 2);
#pragma unroll
            for (int ni = 0; ni < 4; ni++) {
                int c0 = warpN * 32 + ni * 8 + (lane & 3) * 2;
                g_lev[(size_t)r0 * NLEV + c0]           = acc[mi][ni][0];
                g_lev[(size_t)r0 * NLEV + c0 + 1]       = acc[mi][ni][1];
                g_lev[(size_t)(r0 + 8) * NLEV + c0]     = acc[mi][ni][2];
                g_lev[(size_t)(r0 + 8) * NLEV + c0 + 1] = acc[mi][ni][3];
            }
        }
        return;
    }

    // MODE 0: columns are gate-interleaved: col -> (j = col>>2, gate = col&3).
    // Even lane-pair member holds (cc_i, cc_f), odd holds (cc_o, cc_g) for same j.
    const int lane4 = lane & 3;
    const bool evenl = (lane4 & 1) == 0;
    float* outH = d_out;
    float* outC = d_out + (size_t)BSZ * HID;
    int rbase = bm * BM + warpM * 64;
#pragma unroll
    for (int mi = 0; mi < 4; mi++) {
        int r0 = rbase + mi * 16 + (lane >> 2);
#pragma unroll
        for (int ni = 0; ni < 4; ni++) {
            float p0 = __shfl_xor_sync(0xffffffffu, acc[mi][ni][0], 1);
            float p1 = __shfl_xor_sync(0xffffffffu, acc[mi][ni][1], 1);
            float p2 = __shfl_xor_sync(0xffffffffu, acc[mi][ni][2], 1);
            float p3 = __shfl_xor_sync(0xffffffffu, acc[mi][ni][3], 1);
            if (evenl) {
                int j  = (bn * BN + warpN * 32 + ni * 8 + lane4 * 2) >> 2;
                int lv = j >> 4;
                // row r0
                {
                    float iv = sigmoidf_(acc[mi][ni][0]);
                    float fv = sigmoidf_(acc[mi][ni][1]);
                    float ov = sigmoidf_(p0);
                    float gv = tanhf(p1);
                    float cp = c_prev[(size_t)r0 * HID + j];
                    float ih = g_ih[(size_t)r0 * LVL + lv];
                    float fh = g_fh[(size_t)r0 * LVL + lv];
                    float w  = ih * fh;
                    float cn = w * (fv * cp + iv * gv) + (fh - w) * cp + (ih - w) * gv;
                    outC[(size_t)r0 * HID + j] = cn;
                    outH[(size_t)r0 * HID + j] = ov * tanhf(cn);
                }
                // row r0 + 8
                {
                    int r1 = r0 + 8;
                    float iv = sigmoidf_(acc[mi][ni][2]);
                    float fv = sigmoidf_(acc[mi][ni][3]);
                    float ov = sigmoidf_(p2);
                    float gv = tanhf(p3);
                    float cp = c_prev[(size_t)r1 * HID + j];
                    float ih = g_ih[(size_t)r1 * LVL + lv];
                    float fh = g_fh[(size_t)r1 * LVL + lv];
                    float w  = ih * fh;
                    float cn = w * (fv * cp + iv * gv) + (fh - w) * cp + (ih - w) * gv;
                    outC[(size_t)r1 * HID + j] = cn;
                    outH[(size_t)r1 * HID + j] = ov * tanhf(cn);
                }
            }
        }
    }
}

// -------- per-row softmax + cumsum over 64 levels (1 warp / row) --------
__global__ void level_kernel() {
    int row  = blockIdx.x * 8 + (threadIdx.x >> 5);
    int lane = threadIdx.x & 31;
    const float* L = g_lev + (size_t)row * NLEV;
    // cc_i_h = cols [0,64), cc_f_h = cols [64,128)
    float xi0 = L[lane], xi1 = L[32 + lane];
    float xf0 = L[64 + lane], xf1 = L[96 + lane];

    // ---- i_h = forward inclusive cumsum of softmax(cc_f_h) ----
    float m = fmaxf(xf0, xf1);
#pragma unroll
    for (int o = 16; o; o >>= 1) m = fmaxf(m, __shfl_xor_sync(~0u, m, o));
    float e0 = __expf(xf0 - m), e1 = __expf(xf1 - m);
    float s = e0 + e1;
#pragma unroll
    for (int o = 16; o; o >>= 1) s += __shfl_xor_sync(~0u, s, o);
    float inv = 1.0f / s;
    float s0 = e0;
#pragma unroll
    for (int o = 1; o < 32; o <<= 1) { float v = __shfl_up_sync(~0u, s0, o); if (lane >= o) s0 += v; }
    float tot0 = __shfl_sync(~0u, s0, 31);
    float s1 = e1;
#pragma unroll
    for (int o = 1; o < 32; o <<= 1) { float v = __shfl_up_sync(~0u, s1, o); if (lane >= o) s1 += v; }
    g_ih[(size_t)row * LVL + lane]      = s0 * inv;
    g_ih[(size_t)row * LVL + 32 + lane] = (tot0 + s1) * inv;

    // ---- f_h[k] = sum_{s>=k} softmax(cc_i_h)[s] (reverse inclusive cumsum) ----
    float mq = fmaxf(xi0, xi1);
#pragma unroll
    for (int o = 16; o; o >>= 1) mq = fmaxf(mq, __shfl_xor_sync(~0u, mq, o));
    float q0 = __expf(xi0 - mq), q1 = __expf(xi1 - mq);
    float sq = q0 + q1;
#pragma unroll
    for (int o = 16; o; o >>= 1) sq += __shfl_xor_sync(~0u, sq, o);
    float invq = 1.0f / sq;
    // reverse scan of upper half
    float r1 = q1;
#pragma unroll
    for (int o = 1; o < 32; o <<= 1) { float v = __shfl_down_sync(~0u, r1, o); if (lane < 32 - o) r1 += v; }
    float tot1 = __shfl_sync(~0u, r1, 0);
    float r0 = q0;
#pragma unroll
    for (int o = 1; o < 32; o <<= 1) { float v = __shfl_down_sync(~0u, r0, o); if (lane < 32 - o) r0 += v; }
    g_fh[(size_t)row * LVL + lane]      = (r0 + tot1) * invq;
    g_fh[(size_t)row * LVL + 32 + lane] = r1 * invq;
}

extern "C" void kernel_launch(void* const* d_in, const int* in_sizes, int n_in,
                              void* d_out, int out_size) {
    const float* input   = (const float*)d_in[0];
    const float* h_prev  = (const float*)d_in[1];
    const float* c_prev  = (const float*)d_in[2];
    const float* W_lstm  = (const float*)d_in[3];
    const float* W_level = (const float*)d_in[4];
    float* out = (float*)d_out;

    prep_A<<<(BSZ * KDIM / 4) / 256, 256>>>(input, h_prev);
    prep_W<<<((NGATE + NLEV) * (KDIM / 4)) / 256, 256>>>(W_lstm, W_level);
    gemm_kernel<1><<<dim3(1, BSZ / BM), 256>>>(nullptr, nullptr);      // level logits
    level_kernel<<<BSZ / 8, 256>>>();                                  // softmax + cumsum
    gemm_kernel<0><<<dim3(NGATE / BN, BSZ / BM), 256>>>(c_prev, out);  // gates + fused epilogue
}